// round 1
// baseline (speedup 1.0000x reference)
#include <cuda_runtime.h>
#include <cstdint>

// Sliding-window unfold: out[b, i, j] = x[b, i + j]
//   x:   [B, L]        = [128, 8192]  f32
//   out: [B, NW, W]    = [128, 8162, 31] f32   (NW = L - 2*(W/2) = 8162)
//
// Pure bandwidth problem: ~129.5 MB written, ~4 MB read (31x reuse -> L1).
// Strategy: linear output index, float4 (STG.128) coalesced stores, scalar
// L1-hit LDGs for the gather, constant-divide index math.

static constexpr int B_  = 128;
static constexpr int L_  = 8192;
static constexpr int W_  = 31;
static constexpr int R_  = W_ / 2;            // 15
static constexpr int NW_ = L_ - 2 * R_;       // 8162
static constexpr unsigned PER_B = (unsigned)NW_ * W_;   // 253022
static constexpr long long TOTAL = (long long)B_ * PER_B; // 32386816 (divisible by 4)

__global__ __launch_bounds__(256)
void unfold_kernel(const float* __restrict__ x, float4* __restrict__ out, unsigned n4) {
    unsigned t = blockIdx.x * blockDim.x + threadIdx.x;
    if (t >= n4) return;
    unsigned lin = t * 4u;

    float v[4];
#pragma unroll
    for (int k = 0; k < 4; ++k) {
        unsigned l = lin + (unsigned)k;
        unsigned b = l / PER_B;               // const-div -> IMAD.HI
        unsigned r = l - b * PER_B;
        unsigned i = r / (unsigned)W_;        // const-div -> IMAD.HI
        unsigned j = r - i * (unsigned)W_;
        v[k] = __ldg(&x[b * (unsigned)L_ + i + j]);
    }
    out[t] = make_float4(v[0], v[1], v[2], v[3]);
}

extern "C" void kernel_launch(void* const* d_in, const int* in_sizes, int n_in,
                              void* d_out, int out_size) {
    const float* x = (const float*)d_in[0];
    // d_in[1] is win_size (int scalar on device) — fixed at 31 for this problem.
    (void)in_sizes; (void)n_in;

    unsigned n4 = (unsigned)(TOTAL / 4);      // 8,096,704 float4 stores
    const int threads = 256;
    unsigned blocks = (n4 + threads - 1) / threads;
    unfold_kernel<<<blocks, threads>>>(x, (float4*)d_out, n4);
}